// round 1
// baseline (speedup 1.0000x reference)
#include <cuda_runtime.h>

#define N_NODES 30000
#define KNBR    20
#define DIM     128
#define M_TILE  32
#define NTHREADS 256
#define AGG_STRIDE 388     // 384 + 4 pad (keeps float4 alignment, breaks conflicts)
#define KK_TILE 64
#define SMEM_BYTES ((M_TILE*AGG_STRIDE + KK_TILE*DIM) * 4)

__device__ float g_cvec[DIM];

// cos(x) for x in [0, ~1.2e4]: reduce mod pi (3-term Cody-Waite; q < 2^12 so
// q*P1 is exact), then MUFU.COS on |r|<=pi/2 where its error is ~2^-21, then
// sign flip by parity of q. Magic-number rounding gives q and its integer bits.
__device__ __forceinline__ float fast_cos(float x) {
    const float MAGIC = 12582912.0f;               // 1.5 * 2^23
    float qm = fmaf(x, 0.31830988618379067f, MAGIC);
    int   iq = __float_as_int(qm);                 // low bits = integer q
    float q  = qm - MAGIC;
    float r  = fmaf(q, -3.140625f, x);
    r = fmaf(q, -9.67502593994140625e-4f, r);
    r = fmaf(q, -1.5099579909783764e-7f, r);
    float c = __cosf(r);
    return __int_as_float(__float_as_int(c) ^ (iq << 31));
}

// cvec[c] = b2[c] + sum_d cos(time_b[d]) * W2[256+d][c]
__global__ void cvec_kernel(const float* __restrict__ W2,
                            const float* __restrict__ b2,
                            const float* __restrict__ tb) {
    int c = threadIdx.x;
    float acc = b2[c];
    for (int d = 0; d < DIM; ++d)
        acc = fmaf(cosf(tb[d]), W2[(2 * DIM + d) * DIM + c], acc);
    g_cvec[c] = acc;
}

__device__ __forceinline__ void ldW(const float* __restrict__ W, int tile, float4 r[8]) {
    const float4* p = (const float4*)(W + tile * KK_TILE * DIM);
#pragma unroll
    for (int j = 0; j < 8; ++j) r[j] = p[threadIdx.x + j * NTHREADS];
}

__device__ __forceinline__ void stW(float* Ws, const float4 r[8]) {
    float4* p = (float4*)Ws;
#pragma unroll
    for (int j = 0; j < 8; ++j) p[threadIdx.x + j * NTHREADS] = r[j];
}

#define FMA4(ax, bu)                                \
    acc[i][0] = fmaf(ax, (bu).x, acc[i][0]);        \
    acc[i][1] = fmaf(ax, (bu).y, acc[i][1]);        \
    acc[i][2] = fmaf(ax, (bu).z, acc[i][2]);        \
    acc[i][3] = fmaf(ax, (bu).w, acc[i][3]);

__device__ __forceinline__ void gemm_tile(const float* __restrict__ aggS,
                                          const float* __restrict__ Ws,
                                          int kkBase, int rg4, int c4,
                                          float (&acc)[4][4]) {
#pragma unroll 4
    for (int kk4 = 0; kk4 < KK_TILE / 4; ++kk4) {
        float4 a[4], b[4];
#pragma unroll
        for (int i = 0; i < 4; ++i)
            a[i] = *(const float4*)&aggS[(rg4 + i) * AGG_STRIDE + kkBase + kk4 * 4];
#pragma unroll
        for (int u = 0; u < 4; ++u)
            b[u] = *(const float4*)&Ws[(kk4 * 4 + u) * DIM + c4];
#pragma unroll
        for (int i = 0; i < 4; ++i) {
            FMA4(a[i].x, b[0]);
            FMA4(a[i].y, b[1]);
            FMA4(a[i].z, b[2]);
            FMA4(a[i].w, b[3]);
        }
    }
}

__global__ void __launch_bounds__(NTHREADS, 2)
tgs_kernel(const float* __restrict__ node_features,
           const float* __restrict__ timestamps,
           const float* __restrict__ edge_features,
           const int*   __restrict__ neighbors,
           const int*   __restrict__ edge_idxs,
           const float* __restrict__ edge_times,
           const float* __restrict__ time_w,
           const float* __restrict__ time_b,
           const float* __restrict__ W1,
           const float* __restrict__ b1,
           const float* __restrict__ W2,
           float* __restrict__ out) {
    extern __shared__ float smem[];
    float* aggS = smem;                          // [M_TILE][AGG_STRIDE]
    float* Ws   = smem + M_TILE * AGG_STRIDE;    // [KK_TILE][DIM]

    const int tid  = threadIdx.x;
    const int lane = tid & 31;
    const int wid  = tid >> 5;
    const int blk  = blockIdx.x;

    // ---------------- Phase 1: per-node aggregation (sum over K) ----------------
    {
        const float4 tw4 = *(const float4*)(time_w + lane * 4);
        const float4 tb4 = *(const float4*)(time_b + lane * 4);
#pragma unroll
        for (int v = 0; v < 4; ++v) {
            const int m = wid * 4 + v;
            const int n = blk * M_TILE + m;
            float4 an = {0.f, 0.f, 0.f, 0.f};
            float4 at = {0.f, 0.f, 0.f, 0.f};
            float4 ae = {0.f, 0.f, 0.f, 0.f};
            if (n < N_NODES) {
                const float tsn  = timestamps[n];
                const int*   nb_p = neighbors  + n * KNBR;
                const int*   ei_p = edge_idxs  + n * KNBR;
                const float* et_p = edge_times + n * KNBR;
#pragma unroll 5
                for (int k = 0; k < KNBR; ++k) {
                    const int   nb = nb_p[k];
                    const int   ei = ei_p[k];
                    const float et = et_p[k];
                    const float4 f1 = *(const float4*)(node_features + nb * DIM + lane * 4);
                    const float4 f2 = *(const float4*)(edge_features + ei * DIM + lane * 4);
                    an.x += f1.x; an.y += f1.y; an.z += f1.z; an.w += f1.w;
                    ae.x += f2.x; ae.y += f2.y; ae.z += f2.z; ae.w += f2.w;
                    const float dl = tsn - et;
                    at.x += fast_cos(fmaf(dl, tw4.x, tb4.x));
                    at.y += fast_cos(fmaf(dl, tw4.y, tb4.y));
                    at.z += fast_cos(fmaf(dl, tw4.z, tb4.z));
                    at.w += fast_cos(fmaf(dl, tw4.w, tb4.w));
                }
            }
            float* row = aggS + m * AGG_STRIDE + lane * 4;
            *(float4*)(row)       = an;   // cols [0,128)   : neighbor-feature sum
            *(float4*)(row + 128) = at;   // cols [128,256) : time-embedding sum
            *(float4*)(row + 256) = ae;   // cols [256,384) : edge-feature sum
        }
    }

    const int rg4 = (tid >> 5) * 4;   // warp owns 4 rows
    const int c4  = (tid & 31) * 4;   // lane owns 4 cols

    float4 wreg[8];
    ldW(W1, 0, wreg);
    __syncthreads();   // aggS ready

    // ---------------- GEMM1: H = relu(agg @ W1 + K*b1) ----------------
    float acc[4][4];
#pragma unroll
    for (int i = 0; i < 4; ++i)
#pragma unroll
        for (int j = 0; j < 4; ++j) acc[i][j] = 0.f;

#pragma unroll 1
    for (int t = 0; t < 384 / KK_TILE; ++t) {
        stW(Ws, wreg);
        if (t < 384 / KK_TILE - 1) ldW(W1, t + 1, wreg);
        __syncthreads();
        gemm_tile(aggS, Ws, t * KK_TILE, rg4, c4, acc);
        __syncthreads();
    }

    ldW(W2, 0, wreg);   // prefetch W2 tile 0 while epilogue runs

    // Epilogue 1: write H into aggS cols [0,128)
    {
        const float4 b1v = *(const float4*)(b1 + c4);
#pragma unroll
        for (int i = 0; i < 4; ++i) {
            float4 h;
            h.x = fmaxf(fmaf((float)KNBR, b1v.x, acc[i][0]), 0.f);
            h.y = fmaxf(fmaf((float)KNBR, b1v.y, acc[i][1]), 0.f);
            h.z = fmaxf(fmaf((float)KNBR, b1v.z, acc[i][2]), 0.f);
            h.w = fmaxf(fmaf((float)KNBR, b1v.w, acc[i][3]), 0.f);
            *(float4*)&aggS[(rg4 + i) * AGG_STRIDE + c4] = h;
        }
    }
    // Load node_features of this tile into aggS cols [128,256)
    {
        const int m = tid >> 3;
        const int u = tid & 7;
        const int n = blk * M_TILE + m;
#pragma unroll
        for (int v2 = 0; v2 < 4; ++v2) {
            const int col = u * 16 + v2 * 4;
            float4 val = {0.f, 0.f, 0.f, 0.f};
            if (n < N_NODES) val = *(const float4*)(node_features + n * DIM + col);
            *(float4*)&aggS[m * AGG_STRIDE + 128 + col] = val;
        }
    }
    __syncthreads();

    // ---------------- GEMM2: out = [H | nf] @ W2[0:256] + cvec ----------------
    {
        const float4 cv = *(const float4*)&g_cvec[c4];
#pragma unroll
        for (int i = 0; i < 4; ++i) {
            acc[i][0] = cv.x; acc[i][1] = cv.y; acc[i][2] = cv.z; acc[i][3] = cv.w;
        }
    }
#pragma unroll 1
    for (int t = 0; t < 256 / KK_TILE; ++t) {
        stW(Ws, wreg);
        if (t < 256 / KK_TILE - 1) ldW(W2, t + 1, wreg);
        __syncthreads();
        gemm_tile(aggS, Ws, t * KK_TILE, rg4, c4, acc);
        __syncthreads();
    }

#pragma unroll
    for (int i = 0; i < 4; ++i) {
        const int n = blk * M_TILE + rg4 + i;
        if (n < N_NODES) {
            float4 o = {acc[i][0], acc[i][1], acc[i][2], acc[i][3]};
            *(float4*)(out + n * DIM + c4) = o;
        }
    }
}

extern "C" void kernel_launch(void* const* d_in, const int* in_sizes, int n_in,
                              void* d_out, int out_size) {
    const float* node_features = (const float*)d_in[0];
    const float* timestamps    = (const float*)d_in[1];
    const float* edge_features = (const float*)d_in[2];
    const int*   neighbors     = (const int*)d_in[3];
    const int*   edge_idxs     = (const int*)d_in[4];
    const float* edge_times    = (const float*)d_in[5];
    const float* time_w        = (const float*)d_in[6];
    const float* time_b        = (const float*)d_in[7];
    const float* W1            = (const float*)d_in[8];
    const float* b1            = (const float*)d_in[9];
    const float* W2            = (const float*)d_in[10];
    const float* b2            = (const float*)d_in[11];
    float* out = (float*)d_out;

    cudaFuncSetAttribute(tgs_kernel, cudaFuncAttributeMaxDynamicSharedMemorySize, SMEM_BYTES);

    cvec_kernel<<<1, DIM>>>(W2, b2, time_b);

    const int grid = (N_NODES + M_TILE - 1) / M_TILE;
    tgs_kernel<<<grid, NTHREADS, SMEM_BYTES>>>(
        node_features, timestamps, edge_features, neighbors, edge_idxs,
        edge_times, time_w, time_b, W1, b1, W2, out);
}

// round 2
// speedup vs baseline: 1.3841x; 1.3841x over previous
#include <cuda_runtime.h>

#define N_NODES 30000
#define KNBR    20
#define DIM     128
#define M_TILE  32
#define NTHREADS 256
#define AGG_STRIDE 388     // pad: row bank shift = 4, spreads 8-row-apart accesses
#define KK_TILE 64

// smem layout (floats)
#define SM_WS    (M_TILE * AGG_STRIDE)       // 12416
#define SM_COSTB (SM_WS + KK_TILE * DIM)     // +8192
#define SM_CVEC  (SM_COSTB + DIM)
#define SMEM_FLOATS (SM_CVEC + DIM)
#define SMEM_BYTES (SMEM_FLOATS * 4)

typedef unsigned long long u64;

__device__ __forceinline__ u64 fma2(u64 a, u64 b, u64 c) {
    u64 d;
    asm("fma.rn.f32x2 %0, %1, %2, %3;" : "=l"(d) : "l"(a), "l"(b), "l"(c));
    return d;
}
__device__ __forceinline__ u64 pack2(float x) {
    u64 d;
    unsigned r = __float_as_uint(x);
    asm("mov.b64 %0, {%1, %2};" : "=l"(d) : "r"(r), "r"(r));
    return d;
}
__device__ __forceinline__ void unpack2(u64 v, float& lo, float& hi) {
    unsigned a, b;
    asm("mov.b64 {%0, %1}, %2;" : "=r"(a), "=r"(b) : "l"(v));
    lo = __uint_as_float(a);
    hi = __uint_as_float(b);
}

// cos(x), x in [0, ~1.2e4]: Cody-Waite 3-term reduction mod pi (q < 2^12 so
// q*P1 exact), MUFU.COS on |r|<=pi/2, sign flip by parity of q.
__device__ __forceinline__ float fast_cos(float x) {
    const float MAGIC = 12582912.0f;               // 1.5 * 2^23
    float qm = fmaf(x, 0.31830988618379067f, MAGIC);
    int   iq = __float_as_int(qm);
    float q  = qm - MAGIC;
    float r  = fmaf(q, -3.140625f, x);
    r = fmaf(q, -9.67502593994140625e-4f, r);
    r = fmaf(q, -1.5099579909783764e-7f, r);
    float c = __cosf(r);
    return __int_as_float(__float_as_int(c) ^ (iq << 31));
}

__device__ __forceinline__ void ldW(const float* __restrict__ W, int tile, float4 r[8]) {
    const float4* p = (const float4*)(W + tile * KK_TILE * DIM);
#pragma unroll
    for (int j = 0; j < 8; ++j) r[j] = p[threadIdx.x + j * NTHREADS];
}
__device__ __forceinline__ void stW(float* Ws, const float4 r[8]) {
    float4* p = (float4*)Ws;
#pragma unroll
    for (int j = 0; j < 8; ++j) p[threadIdx.x + j * NTHREADS] = r[j];
}

// One KK_TILE-deep GEMM tile. Thread owns rows {r8, r8+8, r8+16, r8+24} and
// cols [coff, coff+4). a-loads: 8 distinct rows/warp, pad-388 spreads banks ->
// 1 phase. b-loads: 4 distinct 16B addrs/warp (broadcast dedup) -> 1 phase.
__device__ __forceinline__ void gemm_tile(const float* __restrict__ aS,
                                          const float* __restrict__ Ws,
                                          int r8, int coff,
                                          u64 (&acc)[4][2]) {
#pragma unroll 4
    for (int kk4 = 0; kk4 < KK_TILE / 4; ++kk4) {
        float a4[4][4];
#pragma unroll
        for (int i = 0; i < 4; ++i)
            *(float4*)a4[i] = *(const float4*)&aS[(r8 + 8 * i) * AGG_STRIDE + kk4 * 4];
        ulonglong2 bv[4];
#pragma unroll
        for (int k = 0; k < 4; ++k)
            bv[k] = *(const ulonglong2*)&Ws[(kk4 * 4 + k) * DIM + coff];
#pragma unroll
        for (int k = 0; k < 4; ++k)
#pragma unroll
            for (int i = 0; i < 4; ++i) {
                u64 aa = pack2(a4[i][k]);
                acc[i][0] = fma2(aa, bv[k].x, acc[i][0]);
                acc[i][1] = fma2(aa, bv[k].y, acc[i][1]);
            }
    }
}

__global__ void __launch_bounds__(NTHREADS, 2)
tgs_kernel(const float* __restrict__ node_features,
           const float* __restrict__ timestamps,
           const float* __restrict__ edge_features,
           const int*   __restrict__ neighbors,
           const int*   __restrict__ edge_idxs,
           const float* __restrict__ edge_times,
           const float* __restrict__ time_w,
           const float* __restrict__ time_b,
           const float* __restrict__ W1,
           const float* __restrict__ b1,
           const float* __restrict__ W2,
           const float* __restrict__ b2,
           float* __restrict__ out) {
    extern __shared__ float smem[];
    float* aggS = smem;                 // [M_TILE][AGG_STRIDE]
    float* Ws   = smem + SM_WS;         // [KK_TILE][DIM]

    const int tid  = threadIdx.x;
    const int lane = tid & 31;
    const int wid  = tid >> 5;
    const int blk  = blockIdx.x;

    // ---------------- Phase 1: per-node aggregation (sum over K) ----------------
    {
        const float4 tw4 = *(const float4*)(time_w + lane * 4);
        const float4 tb4 = *(const float4*)(time_b + lane * 4);
#pragma unroll
        for (int v = 0; v < 4; ++v) {
            const int m = wid * 4 + v;
            const int n = blk * M_TILE + m;
            float4 an = {0.f, 0.f, 0.f, 0.f};
            float4 at = {0.f, 0.f, 0.f, 0.f};
            float4 ae = {0.f, 0.f, 0.f, 0.f};
            if (n < N_NODES) {
                const float tsn  = timestamps[n];
                const int*   nb_p = neighbors  + n * KNBR;
                const int*   ei_p = edge_idxs  + n * KNBR;
                const float* et_p = edge_times + n * KNBR;
#pragma unroll 5
                for (int k = 0; k < KNBR; ++k) {
                    const int   nb = nb_p[k];
                    const int   ei = ei_p[k];
                    const float et = et_p[k];
                    const float4 f1 = *(const float4*)(node_features + nb * DIM + lane * 4);
                    const float4 f2 = *(const float4*)(edge_features + ei * DIM + lane * 4);
                    an.x += f1.x; an.y += f1.y; an.z += f1.z; an.w += f1.w;
                    ae.x += f2.x; ae.y += f2.y; ae.z += f2.z; ae.w += f2.w;
                    const float dl = tsn - et;
                    at.x += fast_cos(fmaf(dl, tw4.x, tb4.x));
                    at.y += fast_cos(fmaf(dl, tw4.y, tb4.y));
                    at.z += fast_cos(fmaf(dl, tw4.z, tb4.z));
                    at.w += fast_cos(fmaf(dl, tw4.w, tb4.w));
                }
            }
            float* row = aggS + m * AGG_STRIDE + lane * 4;
            *(float4*)(row)       = an;   // cols [0,128)
            *(float4*)(row + 128) = at;   // cols [128,256)
            *(float4*)(row + 256) = ae;   // cols [256,384)
        }
    }

    if (tid < DIM) smem[SM_COSTB + tid] = cosf(time_b[tid]);

    const int r8   = lane >> 2;           // rows r8 + 8i
    const int c2   = lane & 3;
    const int coff = wid * 16 + c2 * 4;   // this thread's 4 output columns

    float4 wreg[8];
    ldW(W1, 0, wreg);
    __syncthreads();   // aggS + costb ready

    // cvec[c] = b2[c] + sum_d cos(time_b[d]) * W2[256+d][c]  (per-CTA, cheap)
    if (tid < DIM) {
        float a = b2[tid];
#pragma unroll 16
        for (int d = 0; d < DIM; ++d)
            a = fmaf(smem[SM_COSTB + d], W2[(2 * DIM + d) * DIM + tid], a);
        smem[SM_CVEC + tid] = a;
    }

    // ---------------- GEMM1: H = relu(agg @ W1 + K*b1) ----------------
    u64 acc[4][2];
#pragma unroll
    for (int i = 0; i < 4; ++i) { acc[i][0] = 0ull; acc[i][1] = 0ull; }

#pragma unroll 1
    for (int t = 0; t < 384 / KK_TILE; ++t) {
        stW(Ws, wreg);
        if (t < 384 / KK_TILE - 1) ldW(W1, t + 1, wreg);
        __syncthreads();
        gemm_tile(aggS + t * KK_TILE, Ws, r8, coff, acc);
        __syncthreads();
    }

    ldW(W2, 0, wreg);   // prefetch W2 tile 0 while epilogue runs

    // Epilogue 1: H -> aggS cols [0,128)
    {
        const float4 b1v = *(const float4*)&b1[coff];
#pragma unroll
        for (int i = 0; i < 4; ++i) {
            float4 h;
            unpack2(acc[i][0], h.x, h.y);
            unpack2(acc[i][1], h.z, h.w);
            h.x = fmaxf(fmaf((float)KNBR, b1v.x, h.x), 0.f);
            h.y = fmaxf(fmaf((float)KNBR, b1v.y, h.y), 0.f);
            h.z = fmaxf(fmaf((float)KNBR, b1v.z, h.z), 0.f);
            h.w = fmaxf(fmaf((float)KNBR, b1v.w, h.w), 0.f);
            *(float4*)&aggS[(r8 + 8 * i) * AGG_STRIDE + coff] = h;
        }
    }
    // node_features of this tile -> aggS cols [128,256)
    {
        const int m = tid >> 3;
        const int u = tid & 7;
        const int n = blk * M_TILE + m;
#pragma unroll
        for (int v2 = 0; v2 < 4; ++v2) {
            const int col = u * 16 + v2 * 4;
            float4 val = {0.f, 0.f, 0.f, 0.f};
            if (n < N_NODES) val = *(const float4*)(node_features + n * DIM + col);
            *(float4*)&aggS[m * AGG_STRIDE + 128 + col] = val;
        }
    }
    __syncthreads();

    // ---------------- GEMM2: out = [H | nf] @ W2[0:256] + cvec ----------------
    {
        const u64 cv0 = *(const u64*)&smem[SM_CVEC + coff];
        const u64 cv1 = *(const u64*)&smem[SM_CVEC + coff + 2];
#pragma unroll
        for (int i = 0; i < 4; ++i) { acc[i][0] = cv0; acc[i][1] = cv1; }
    }
#pragma unroll 1
    for (int t = 0; t < 256 / KK_TILE; ++t) {
        stW(Ws, wreg);
        if (t < 256 / KK_TILE - 1) ldW(W2, t + 1, wreg);
        __syncthreads();
        gemm_tile(aggS + t * KK_TILE, Ws, r8, coff, acc);
        __syncthreads();
    }

#pragma unroll
    for (int i = 0; i < 4; ++i) {
        const int n = blk * M_TILE + r8 + 8 * i;
        if (n < N_NODES) {
            float4 o;
            unpack2(acc[i][0], o.x, o.y);
            unpack2(acc[i][1], o.z, o.w);
            *(float4*)(out + n * DIM + coff) = o;
        }
    }
}

extern "C" void kernel_launch(void* const* d_in, const int* in_sizes, int n_in,
                              void* d_out, int out_size) {
    const float* node_features = (const float*)d_in[0];
    const float* timestamps    = (const float*)d_in[1];
    const float* edge_features = (const float*)d_in[2];
    const int*   neighbors     = (const int*)d_in[3];
    const int*   edge_idxs     = (const int*)d_in[4];
    const float* edge_times    = (const float*)d_in[5];
    const float* time_w        = (const float*)d_in[6];
    const float* time_b        = (const float*)d_in[7];
    const float* W1            = (const float*)d_in[8];
    const float* b1            = (const float*)d_in[9];
    const float* W2            = (const float*)d_in[10];
    const float* b2            = (const float*)d_in[11];
    float* out = (float*)d_out;

    cudaFuncSetAttribute(tgs_kernel, cudaFuncAttributeMaxDynamicSharedMemorySize, SMEM_BYTES);

    const int grid = (N_NODES + M_TILE - 1) / M_TILE;
    tgs_kernel<<<grid, NTHREADS, SMEM_BYTES>>>(
        node_features, timestamps, edge_features, neighbors, edge_idxs,
        edge_times, time_w, time_b, W1, b1, W2, b2, out);
}